// round 3
// baseline (speedup 1.0000x reference)
#include <cuda_runtime.h>
#include <math_constants.h>

#define IW 224
#define IH 224
#define CCH 32

// Load the 8-float window [xbase-2, xbase+6) of input row `ry` into R[0..7].
// One aligned LDG.128 + 4 shuffles; lanes 0/31 patch halos with scalar loads.
// Out-of-bounds (rows or cols) -> -inf (tropical neutral).
__device__ __forceinline__ void load_row8(float (&R)[8], const float* __restrict__ x,
                                          int ry, int xbase) {
    const float NEG = -CUDART_INF_F;
    bool rv = ((unsigned)ry < (unsigned)IH);
    const float* row = x + ry * IW;
    float4 c;
    if (rv && (xbase < IW)) {
        c = *(const float4*)(row + xbase);
    } else {
        c.x = NEG; c.y = NEG; c.z = NEG; c.w = NEG;
    }
    float lz = __shfl_up_sync(0xffffffffu, c.z, 1);
    float lw = __shfl_up_sync(0xffffffffu, c.w, 1);
    float rx = __shfl_down_sync(0xffffffffu, c.x, 1);
    float ryv = __shfl_down_sync(0xffffffffu, c.y, 1);
    int lane = threadIdx.x & 31;
    if (lane == 0) {
        int c0 = xbase - 2;           // -2 for tile 0, 126 for tile 1
        lz = (rv && c0 >= 0) ? row[c0] : NEG;
        lw = (rv && c0 + 1 >= 0) ? row[c0 + 1] : NEG;
    }
    if (lane == 31) {
        int c0 = xbase + 4;           // 128 for tile 0, 256 for tile 1
        rx = (rv && c0 < IW) ? row[c0] : NEG;
        ryv = (rv && c0 + 1 < IW) ? row[c0 + 1] : NEG;
    }
    R[0] = lz; R[1] = lw; R[2] = c.x; R[3] = c.y;
    R[4] = c.z; R[5] = c.w; R[6] = rx; R[7] = ryv;
}

// out[b,c,y,x] = max_{i,j in [0,5)} x[b,c,y+i-2,x+j-2] + kernel[c,0,4-i,4-j]
// (out-of-bounds input = -inf)
__global__ void __launch_bounds__(128, 4)
tropical_conv2d_kernel(const float* __restrict__ x,
                       const float* __restrict__ kw,
                       float* __restrict__ out) {
    const float NEG = -CUDART_INF_F;
    int bx = blockIdx.x;
    int tile = bx & 1;          // x-tile: cols [0,128) or [128,224)
    int img = bx >> 1;          // b*C + c
    int lane = threadIdx.x & 31;
    int warp = threadIdx.x >> 5;
    int xbase = tile * 128 + lane * 4;
    bool do_store = (xbase < IW);

    const float* xi = x + (size_t)img * (IH * IW);
    float* oi = out + (size_t)img * (IH * IW);
    int c = img & (CCH - 1);
    const float* kc = kw + c * 25;

    // wt[i*5+j] = kernel[c,0,4-i,4-j] = kc[24 - (i*5+j)]
    float wt[25];
#pragma unroll
    for (int t = 0; t < 25; ++t) wt[t] = __ldg(kc + (24 - t));

    int y0 = warp * 56;         // 4 warps x 56 rows = full 224-row column
    float R[5][8];
#pragma unroll
    for (int r = 0; r < 5; ++r) load_row8(R[r], xi, y0 - 2 + r, xbase);

    float* orow = oi + y0 * IW + xbase;
#pragma unroll 5
    for (int s = 0; s < 56; ++s) {
        float a0 = NEG, a1 = NEG, a2 = NEG, a3 = NEG;
#pragma unroll
        for (int i = 0; i < 5; ++i) {
#pragma unroll
            for (int j = 0; j < 5; ++j) {
                float wv = wt[i * 5 + j];
                a0 = fmaxf(a0, R[i][j] + wv);
                a1 = fmaxf(a1, R[i][j + 1] + wv);
                a2 = fmaxf(a2, R[i][j + 2] + wv);
                a3 = fmaxf(a3, R[i][j + 3] + wv);
            }
        }
        if (do_store) {
            *(float4*)orow = make_float4(a0, a1, a2, a3);
        }
        orow += IW;
        // slide window down one row (unroll-5 lets ptxas rename these away)
#pragma unroll
        for (int r = 0; r < 4; ++r)
#pragma unroll
            for (int k = 0; k < 8; ++k) R[r][k] = R[r + 1][k];
        load_row8(R[4], xi, y0 + s + 3, xbase);
    }
}

extern "C" void kernel_launch(void* const* d_in, const int* in_sizes, int n_in,
                              void* d_out, int out_size) {
    const float* x = (const float*)d_in[0];   // (8,32,224,224) fp32
    const float* k = (const float*)d_in[1];   // (32,1,5,5) fp32
    float* out = (float*)d_out;               // (8,32,224,224) fp32
    // 256 images x 2 x-tiles; 128 threads = 4 warps x 56-row strips
    tropical_conv2d_kernel<<<512, 128>>>(x, k, out);
}